// round 3
// baseline (speedup 1.0000x reference)
#include <cuda_runtime.h>

// PolylineEncoder:
//   polylines      [32,512,64,9]  f32
//   polylines_mask [32,512,64]    int32 (nonzero = valid)
//   W1 [9,128], b1 [128], W2 [128,128], b2 [128]  f32
//   out [32,512,128] f32
//
// per polyline: h = relu(x @ W1 + b1); feat = h @ W2 + b2;
//   feat[invalid] = -1e9; pooled = max over n; all-invalid -> 0.
//
// 256 threads = two independent 128-thread halves, each owning a stream of 8
// polylines; W2 staged once in smem and shared. 8 warps/SM (2 per SMSP) to
// cover LDS latency that limited the 128-thread version.

#define NPTS 64
#define CIN 9
#define HID 128
#define POLYS_PER_HALF 8
#define POLYS_PER_CTA 16
#define HT_STRIDE 68          // 64 + 4 pad: 16B-aligned rows, breaks bank conflicts
#define NEG_INF_F (-1e9f)

#define SMEM_W2   0                                   // 16384 floats = 64 KB
#define SMEM_HT   (HID * HID)                         // 2 x 128*68   = 69632 B
#define SMEM_XS   (SMEM_HT + 2 * HID * HT_STRIDE)     // 2 x 576
#define SMEM_MSK  (SMEM_XS + 2 * NPTS * CIN)          // 2 x 64 ints
#define SMEM_FLOATS (SMEM_MSK + 2 * NPTS)
#define SMEM_BYTES  (SMEM_FLOATS * 4)                 // 140288 B

extern __shared__ float smem[];

__global__ void __launch_bounds__(256)
polyline_encoder_kernel(const float* __restrict__ poly,
                        const int*   __restrict__ mask,
                        const float* __restrict__ W1,
                        const float* __restrict__ b1,
                        const float* __restrict__ W2,
                        const float* __restrict__ b2,
                        float* __restrict__ out)
{
    float* W2s = smem + SMEM_W2;

    const int tid  = threadIdx.x;
    const int half = tid >> 7;     // 0/1: which polyline stream
    const int ht   = tid & 127;    // thread id within the half

    float* hT  = smem + SMEM_HT  + half * (HID * HT_STRIDE);
    float* xs  = smem + SMEM_XS  + half * (NPTS * CIN);
    int*   msk = (int*)(smem + SMEM_MSK) + half * NPTS;

    // ---- stage W2 into smem once per CTA (coalesced float4, all 256 threads) ----
    {
        const float4* g = (const float4*)W2;
        float4* s = (float4*)W2s;
        #pragma unroll
        for (int i = 0; i < 16; ++i)            // 16 * 256 = 4096 float4 = 64 KB
            s[i * 256 + tid] = g[i * 256 + tid];
    }

    // ---- per-thread layer-1 weights: thread ht computes hidden channel hh = ht ----
    float w1r[CIN];
    #pragma unroll
    for (int c = 0; c < CIN; ++c) w1r[c] = W1[c * HID + ht];
    const float b1r = b1[ht];

    // ---- thread tile mapping for the 64x128 GEMM: 8n x 8d per thread ----
    const int dt = ht >> 3;    // 0..15  -> d0 = dt*8
    const int nt = ht & 7;     // 0..7   -> n0 = nt*8

    float b2r[8];
    #pragma unroll
    for (int j = 0; j < 8; ++j) b2r[j] = b2[dt * 8 + j];

    for (int pp = 0; pp < POLYS_PER_HALF; ++pp) {
        const int bp = blockIdx.x * POLYS_PER_CTA + half * POLYS_PER_HALF + pp;

        // previous iteration's GEMM/epilogue reads of hT and msk must be done
        __syncthreads();

        // ---- stage this polyline's points + mask ----
        const float* xg = poly + (size_t)bp * (NPTS * CIN);
        for (int i = ht; i < NPTS * CIN; i += 128) xs[i] = xg[i];
        if (ht < NPTS) msk[ht] = mask[(size_t)bp * NPTS + ht];
        __syncthreads();

        // ---- layer 1: hT[hh][n] = relu(b1 + x[n,:] . W1[:,hh]), hh = ht ----
        #pragma unroll 4
        for (int n = 0; n < NPTS; ++n) {
            float a = b1r;
            #pragma unroll
            for (int c = 0; c < CIN; ++c) a = fmaf(xs[n * CIN + c], w1r[c], a);
            hT[ht * HT_STRIDE + n] = fmaxf(a, 0.0f);
        }
        __syncthreads();

        // ---- GEMM: feat[n][d] = sum_hh hT[hh][n] * W2[hh][d] ----
        float acc[8][8];
        #pragma unroll
        for (int i = 0; i < 8; ++i)
            #pragma unroll
            for (int j = 0; j < 8; ++j) acc[i][j] = 0.0f;

        const float4* hbase = ((const float4*)hT)  + nt * 2;  // row stride 17 float4
        const float4* wbase = ((const float4*)W2s) + dt * 2;  // row stride 32 float4

        #pragma unroll 2
        for (int hh = 0; hh < HID; ++hh) {
            const float4 ha = hbase[hh * (HT_STRIDE / 4)];
            const float4 hb = hbase[hh * (HT_STRIDE / 4) + 1];
            const float4 wa = wbase[hh * (HID / 4)];
            const float4 wb = wbase[hh * (HID / 4) + 1];
            const float hv[8] = {ha.x, ha.y, ha.z, ha.w, hb.x, hb.y, hb.z, hb.w};
            const float wv[8] = {wa.x, wa.y, wa.z, wa.w, wb.x, wb.y, wb.z, wb.w};
            #pragma unroll
            for (int i = 0; i < 8; ++i)
                #pragma unroll
                for (int j = 0; j < 8; ++j)
                    acc[i][j] = fmaf(hv[i], wv[j], acc[i][j]);
        }

        // ---- masked max over this thread's 8 points + validity OR ----
        float mx[8];
        #pragma unroll
        for (int j = 0; j < 8; ++j) mx[j] = NEG_INF_F;
        int sv = 0;
        #pragma unroll
        for (int i = 0; i < 8; ++i) {
            const int m = msk[nt * 8 + i];
            sv |= m;
            if (m != 0) {
                #pragma unroll
                for (int j = 0; j < 8; ++j) mx[j] = fmaxf(mx[j], acc[i][j]);
            }
        }

        // ---- reduce across the 8 n-tiles (8 consecutive lanes nt=0..7) ----
        #pragma unroll
        for (int off = 1; off < 8; off <<= 1) {
            #pragma unroll
            for (int j = 0; j < 8; ++j) {
                const float o = __shfl_xor_sync(0xffffffffu, mx[j], off);
                mx[j] = fmaxf(mx[j], o);
            }
            sv |= __shfl_xor_sync(0xffffffffu, sv, off);
        }

        // ---- write: +b2 hoisted out of the max (constant over n) ----
        if (nt == 0) {
            float4 o0, o1;
            if (sv != 0) {
                o0 = make_float4(mx[0] + b2r[0], mx[1] + b2r[1],
                                 mx[2] + b2r[2], mx[3] + b2r[3]);
                o1 = make_float4(mx[4] + b2r[4], mx[5] + b2r[5],
                                 mx[6] + b2r[6], mx[7] + b2r[7]);
            } else {
                o0 = make_float4(0.f, 0.f, 0.f, 0.f);
                o1 = make_float4(0.f, 0.f, 0.f, 0.f);
            }
            float4* og = (float4*)(out + (size_t)bp * HID + dt * 8);
            og[0] = o0;
            og[1] = o1;
        }
    }
}

extern "C" void kernel_launch(void* const* d_in, const int* in_sizes, int n_in,
                              void* d_out, int out_size)
{
    const float* poly = (const float*)d_in[0];
    const int*   mask = (const int*)  d_in[1];
    const float* W1   = (const float*)d_in[2];
    const float* b1   = (const float*)d_in[3];
    const float* W2   = (const float*)d_in[4];
    const float* b2   = (const float*)d_in[5];
    float* out = (float*)d_out;

    const int n_poly = in_sizes[1] / NPTS;          // B*P = 16384
    const int grid = n_poly / POLYS_PER_CTA;        // 1024

    cudaFuncSetAttribute(polyline_encoder_kernel,
                         cudaFuncAttributeMaxDynamicSharedMemorySize, SMEM_BYTES);
    polyline_encoder_kernel<<<grid, 256, SMEM_BYTES>>>(poly, mask, W1, b1, W2, b2, out);
}

// round 5
// speedup vs baseline: 2.1511x; 2.1511x over previous
#include <cuda_runtime.h>
#include <cuda_bf16.h>
#include <stdint.h>

// PolylineEncoder via warp-level bf16 HMMA (mma.sync, baseline PTX — tcgen05 is
// unavailable: harness emits compute_103 PTX without the 'a' feature set).
//   per polyline: h = relu(x@W1+b1); feat = h@W2+b2; masked max over 64 pts.
// 3-term bf16 hi/lo split (hh + hl + lh) for fp32-grade accuracy.

#define NEG_INF_F (-1e9f)
#define NT 256
#define TILE_PTS 256   // 4 polylines per tile

__device__ __align__(16) uint4 g_bfrag[8 * 16 * 32];   // W2 fragments, 64 KB

// smem byte offsets
#define SM_W1   0        // 9*128*4 = 4608
#define SM_B1   4608     // 512
#define SM_B2   5120     // 512
#define SM_XS   5632     // 256*9*4 = 9216
#define SM_MSK  14848    // 256*4
#define SM_FLG  15872    // 8*4
#define SM_RED  16384    // 8*128*4 = 4096
#define SM_BF   20480    // 65536
#define SM_HHI  86016    // 65536 (256 rows x 64 words)
#define SM_HLO  151552   // 65536
#define SM_BYTES 217088

// swizzled word index into an h plane: row p (0..255), word w (0..63; word = bf16 pair)
// conflict-free for STS (32 consecutive p, fixed w) AND for A-frag LDS (8 rows x 4 cols)
__device__ __forceinline__ uint32_t hword(int p, int w) {
    return (uint32_t)(p * 64 + ((w + 4 * (p & 7) + ((p >> 3) & 3)) & 63));
}

__device__ __forceinline__ void mma16816(float acc[4], const uint32_t a[4],
                                         uint32_t b0, uint32_t b1) {
    asm volatile("mma.sync.aligned.m16n8k16.row.col.f32.bf16.bf16.f32 "
                 "{%0,%1,%2,%3}, {%4,%5,%6,%7}, {%8,%9}, {%0,%1,%2,%3};"
                 : "+f"(acc[0]), "+f"(acc[1]), "+f"(acc[2]), "+f"(acc[3])
                 : "r"(a[0]), "r"(a[1]), "r"(a[2]), "r"(a[3]), "r"(b0), "r"(b1));
}

__device__ __forceinline__ uint32_t bsplit(float v0, float v1, uint32_t& lo) {
    const __nv_bfloat16 h0 = __float2bfloat16(v0), h1 = __float2bfloat16(v1);
    const __nv_bfloat16 l0 = __float2bfloat16(v0 - __bfloat162float(h0));
    const __nv_bfloat16 l1 = __float2bfloat16(v1 - __bfloat162float(h1));
    lo = (uint32_t)__bfloat16_as_ushort(l0) | ((uint32_t)__bfloat16_as_ushort(l1) << 16);
    return (uint32_t)__bfloat16_as_ushort(h0) | ((uint32_t)__bfloat16_as_ushort(h1) << 16);
}

// ---- prep: pack W2 into mma B fragments (col-major), hi+lo interleaved ----
__global__ void prep_kernel(const float* __restrict__ W2) {
    const int idx = blockIdx.x * blockDim.x + threadIdx.x;
    if (idx >= 8 * 16 * 32) return;
    const int lane = idx & 31, nf = (idx >> 5) & 15, s = idx >> 9;
    const int k0 = s * 16 + 2 * (lane & 3);
    const int n  = nf * 8 + (lane >> 2);
    uint32_t l0, l1;
    const uint32_t h0 = bsplit(W2[k0 * 128 + n],       W2[(k0 + 1) * 128 + n], l0);
    const uint32_t h1 = bsplit(W2[(k0 + 8) * 128 + n], W2[(k0 + 9) * 128 + n], l1);
    g_bfrag[idx] = make_uint4(h0, h1, l0, l1);
}

extern __shared__ unsigned char smB[];

__global__ void __launch_bounds__(NT)
poly_mma_kernel(const float* __restrict__ poly, const int* __restrict__ mask,
                const float* __restrict__ W1g, const float* __restrict__ b1g,
                const float* __restrict__ b2g, float* __restrict__ out, int ntiles)
{
    const int tid = threadIdx.x, wid = tid >> 5, lane = tid & 31;
    float* W1s = (float*)(smB + SM_W1);
    float* b1s = (float*)(smB + SM_B1);
    float* b2s = (float*)(smB + SM_B2);
    float* xsf = (float*)(smB + SM_XS);
    int*   msks = (int*)(smB + SM_MSK);
    uint32_t* flgs = (uint32_t*)(smB + SM_FLG);
    float* red = (float*)(smB + SM_RED);
    uint32_t* hhi = (uint32_t*)(smB + SM_HHI);
    uint32_t* hlo = (uint32_t*)(smB + SM_HLO);

    {   // stage constants once
        uint4* d4 = (uint4*)(smB + SM_BF);
        #pragma unroll
        for (int i = tid; i < 4096; i += NT) d4[i] = g_bfrag[i];
        for (int i = tid; i < 1152; i += NT) W1s[i] = W1g[i];
        if (tid < 128) { b1s[tid] = b1g[tid]; b2s[tid] = b2g[tid]; }
    }

    const int g = tid & 63, q = tid >> 6;       // layer-1 mapping
    const int lr = lane >> 2, lc = lane & 3;    // fragment lane coords
    const int mbase = 32 * wid;                 // warp's point rows

    for (int tile = blockIdx.x; tile < ntiles; tile += gridDim.x) {
        __syncthreads();

        // ---- stage x + mask ----
        const float* xg = poly + (size_t)tile * (TILE_PTS * 9);
        #pragma unroll
        for (int r = 0; r < 9; ++r) xsf[tid + 256 * r] = xg[tid + 256 * r];
        const int mv = mask[(size_t)tile * TILE_PTS + tid];
        msks[tid] = mv;
        const uint32_t bal = __ballot_sync(0xffffffffu, mv != 0);
        if (lane == 0) flgs[wid] = bal;
        __syncthreads();

        // ---- layer 1 (fp32) -> h bf16 hi/lo planes ----
        #pragma unroll 1
        for (int j = 0; j < 4; ++j) {
            const int p = g + 64 * j;
            float x[9];
            #pragma unroll
            for (int c = 0; c < 9; ++c) x[c] = xsf[p * 9 + c];
            #pragma unroll 4
            for (int i = 0; i < 16; ++i) {
                const int hh = q * 32 + 2 * i;
                float a0 = b1s[hh], a1 = b1s[hh + 1];
                #pragma unroll
                for (int c = 0; c < 9; ++c) {
                    a0 = fmaf(x[c], W1s[c * 128 + hh], a0);
                    a1 = fmaf(x[c], W1s[c * 128 + hh + 1], a1);
                }
                a0 = fmaxf(a0, 0.0f);
                a1 = fmaxf(a1, 0.0f);
                uint32_t lo;
                const uint32_t hi = bsplit(a0, a1, lo);
                const uint32_t wv = hword(p, q * 16 + i);
                hhi[wv] = hi;
                hlo[wv] = lo;
            }
        }
        __syncthreads();

        // ---- layer 2: 3-term bf16 mma, masked max epilogue ----
        int m00 = msks[mbase + lr] != 0,      m01 = msks[mbase + lr + 8] != 0;
        int m10 = msks[mbase + 16 + lr] != 0, m11 = msks[mbase + 24 + lr] != 0;

        #pragma unroll 1
        for (int nh = 0; nh < 2; ++nh) {
            float acc[2][8][4];
            #pragma unroll
            for (int mi = 0; mi < 2; ++mi)
                #pragma unroll
                for (int nf = 0; nf < 8; ++nf)
                    #pragma unroll
                    for (int e = 0; e < 4; ++e) acc[mi][nf][e] = 0.0f;

            #pragma unroll 1
            for (int s = 0; s < 8; ++s) {
                uint32_t ah[2][4], al[2][4];
                #pragma unroll
                for (int mi = 0; mi < 2; ++mi) {
                    const int r0 = mbase + 16 * mi + lr;
                    const int w0 = 8 * s + lc;
                    ah[mi][0] = hhi[hword(r0,     w0)];
                    ah[mi][1] = hhi[hword(r0 + 8, w0)];
                    ah[mi][2] = hhi[hword(r0,     w0 + 4)];
                    ah[mi][3] = hhi[hword(r0 + 8, w0 + 4)];
                    al[mi][0] = hlo[hword(r0,     w0)];
                    al[mi][1] = hlo[hword(r0 + 8, w0)];
                    al[mi][2] = hlo[hword(r0,     w0 + 4)];
                    al[mi][3] = hlo[hword(r0 + 8, w0 + 4)];
                }
                #pragma unroll
                for (int nf = 0; nf < 8; ++nf) {
                    const uint4 B = *(const uint4*)(smB + SM_BF +
                        (size_t)(((s * 16) + nh * 8 + nf) * 32 + lane) * 16);
                    #pragma unroll
                    for (int mi = 0; mi < 2; ++mi) {
                        mma16816(acc[mi][nf], ah[mi], B.x, B.y);   // hi*hi
                        mma16816(acc[mi][nf], ah[mi], B.z, B.w);   // hi*lo
                        mma16816(acc[mi][nf], al[mi], B.x, B.y);   // lo*hi
                    }
                }
            }

            // epilogue: masked max over the warp's 32 points
            #pragma unroll
            for (int nf = 0; nf < 8; ++nf) {
                float e0 = NEG_INF_F, e1 = NEG_INF_F;
                if (m00) { e0 = fmaxf(e0, acc[0][nf][0]); e1 = fmaxf(e1, acc[0][nf][1]); }
                if (m01) { e0 = fmaxf(e0, acc[0][nf][2]); e1 = fmaxf(e1, acc[0][nf][3]); }
                if (m10) { e0 = fmaxf(e0, acc[1][nf][0]); e1 = fmaxf(e1, acc[1][nf][1]); }
                if (m11) { e0 = fmaxf(e0, acc[1][nf][2]); e1 = fmaxf(e1, acc[1][nf][3]); }
                #pragma unroll
                for (int off = 4; off < 32; off <<= 1) {
                    e0 = fmaxf(e0, __shfl_xor_sync(0xffffffffu, e0, off));
                    e1 = fmaxf(e1, __shfl_xor_sync(0xffffffffu, e1, off));
                }
                if (lane < 4) {
                    const int n = nh * 64 + nf * 8 + 2 * lane;
                    red[wid * 128 + n]     = e0;
                    red[wid * 128 + n + 1] = e1;
                }
            }
        }
        __syncthreads();

        // ---- final: combine warp pairs per polyline, +b2, any-valid ----
        {
            const int d = tid & 127, pj = tid >> 7;
            #pragma unroll
            for (int k = 0; k < 2; ++k) {
                const int pp = pj + 2 * k;     // polyline within tile (0..3)
                const float v = fmaxf(red[(2 * pp) * 128 + d],
                                      red[(2 * pp + 1) * 128 + d]);
                const uint32_t av = flgs[2 * pp] | flgs[2 * pp + 1];
                out[((size_t)tile * 4 + pp) * 128 + d] = av ? v + b2s[d] : 0.0f;
            }
        }
    }
}

extern "C" void kernel_launch(void* const* d_in, const int* in_sizes, int n_in,
                              void* d_out, int out_size)
{
    const float* poly = (const float*)d_in[0];
    const int*   mask = (const int*)  d_in[1];
    const float* W1   = (const float*)d_in[2];
    const float* b1   = (const float*)d_in[3];
    const float* W2   = (const float*)d_in[4];
    const float* b2   = (const float*)d_in[5];
    float* out = (float*)d_out;

    const int npoints = in_sizes[0] / 9;           // 1,048,576
    const int ntiles  = npoints / TILE_PTS;        // 4096

    prep_kernel<<<16, 256>>>(W2);

    cudaFuncSetAttribute(poly_mma_kernel,
                         cudaFuncAttributeMaxDynamicSharedMemorySize, SM_BYTES);
    poly_mma_kernel<<<148, NT, SM_BYTES>>>(poly, mask, W1, b1, b2, out, ntiles);
}

// round 6
// speedup vs baseline: 2.4464x; 1.1373x over previous
#include <cuda_runtime.h>
#include <cuda_bf16.h>
#include <stdint.h>

// PolylineEncoder via warp-level bf16 HMMA, 3-term hi/lo split.
// R5: 128-pt tiles + W2 fragments via L1 LDG -> smem 76 KB -> 2 CTAs/SM
// so one CTA's MMA phase overlaps the other's FFMA/epilogue phases.

#define NEG_INF_F (-1e9f)
#define NT 256
#define TILE_PTS 128   // 2 polylines per tile

__device__ __align__(16) uint4 g_bfrag[8 * 16 * 32];   // W2 fragments, 64 KB (L1-resident)

// smem byte offsets (total 78464)
#define SM_W1   0        // 9*128*4 = 4608
#define SM_B1   4608     // 512
#define SM_B2   5120     // 512
#define SM_XS   5632     // 128*9*4 = 4608
#define SM_MSK  10240    // 128*4
#define SM_FLG  10752    // 4*4 (+pad)
#define SM_RED  10816    // 4*128*4 = 2048
#define SM_HHI  12928    // 128*64*4 = 32768
#define SM_HLO  45696    // 32768
#define SM_BYTES 78464

// swizzled word index into an h plane: row p (0..127), word w (0..63)
// conflict-free for layer-1 STS.32 (32 consecutive p, fixed w) and for
// A-fragment LDS.32 (8 rows x 4 cols within a warp).
__device__ __forceinline__ uint32_t hword(int p, int w) {
    return (uint32_t)(p * 64 + ((w + 4 * (p & 7) + ((p >> 3) & 3)) & 63));
}

__device__ __forceinline__ void mma16816(float acc[4], const uint32_t a[4],
                                         uint32_t b0, uint32_t b1) {
    asm volatile("mma.sync.aligned.m16n8k16.row.col.f32.bf16.bf16.f32 "
                 "{%0,%1,%2,%3}, {%4,%5,%6,%7}, {%8,%9}, {%0,%1,%2,%3};"
                 : "+f"(acc[0]), "+f"(acc[1]), "+f"(acc[2]), "+f"(acc[3])
                 : "r"(a[0]), "r"(a[1]), "r"(a[2]), "r"(a[3]), "r"(b0), "r"(b1));
}

__device__ __forceinline__ uint32_t bsplit(float v0, float v1, uint32_t& lo) {
    const __nv_bfloat16 h0 = __float2bfloat16(v0), h1 = __float2bfloat16(v1);
    const __nv_bfloat16 l0 = __float2bfloat16(v0 - __bfloat162float(h0));
    const __nv_bfloat16 l1 = __float2bfloat16(v1 - __bfloat162float(h1));
    lo = (uint32_t)__bfloat16_as_ushort(l0) | ((uint32_t)__bfloat16_as_ushort(l1) << 16);
    return (uint32_t)__bfloat16_as_ushort(h0) | ((uint32_t)__bfloat16_as_ushort(h1) << 16);
}

// ---- prep: pack W2 into mma B fragments (col-major), hi+lo interleaved ----
__global__ void prep_kernel(const float* __restrict__ W2) {
    const int idx = blockIdx.x * blockDim.x + threadIdx.x;
    if (idx >= 8 * 16 * 32) return;
    const int lane = idx & 31, nf = (idx >> 5) & 15, s = idx >> 9;
    const int k0 = s * 16 + 2 * (lane & 3);
    const int n  = nf * 8 + (lane >> 2);
    uint32_t l0, l1;
    const uint32_t h0 = bsplit(W2[k0 * 128 + n],       W2[(k0 + 1) * 128 + n], l0);
    const uint32_t h1 = bsplit(W2[(k0 + 8) * 128 + n], W2[(k0 + 9) * 128 + n], l1);
    g_bfrag[idx] = make_uint4(h0, h1, l0, l1);
}

extern __shared__ unsigned char smB[];

__global__ void __launch_bounds__(NT, 2)
poly_mma_kernel(const float* __restrict__ poly, const int* __restrict__ mask,
                const float* __restrict__ W1g, const float* __restrict__ b1g,
                const float* __restrict__ b2g, float* __restrict__ out, int ntiles)
{
    const int tid = threadIdx.x, wid = tid >> 5, lane = tid & 31;
    float* W1s = (float*)(smB + SM_W1);
    float* b1s = (float*)(smB + SM_B1);
    float* b2s = (float*)(smB + SM_B2);
    float* xsf = (float*)(smB + SM_XS);
    int*   msks = (int*)(smB + SM_MSK);
    uint32_t* flgs = (uint32_t*)(smB + SM_FLG);
    float* red = (float*)(smB + SM_RED);
    uint32_t* hhi = (uint32_t*)(smB + SM_HHI);
    uint32_t* hlo = (uint32_t*)(smB + SM_HLO);

    {   // stage constants once
        for (int i = tid; i < 1152; i += NT) W1s[i] = W1g[i];
        if (tid < 128) { b1s[tid] = b1g[tid]; b2s[tid] = b2g[tid]; }
    }

    const int p1 = tid & 127, q1 = tid >> 7;    // layer-1: point, hh-half
    const int lr = lane >> 2, lc = lane & 3;    // fragment lane coords
    const int mq = wid & 3, nh = wid >> 2;      // warp = (M-quad, N-half)
    const int mbase = 32 * mq;

    for (int tile = blockIdx.x; tile < ntiles; tile += gridDim.x) {
        __syncthreads();

        // ---- stage x + mask ----
        const float* xg = poly + (size_t)tile * (TILE_PTS * 9);
        #pragma unroll
        for (int i = tid; i < TILE_PTS * 9; i += NT) xsf[i] = xg[i];
        if (tid < TILE_PTS) {
            const int mv = mask[(size_t)tile * TILE_PTS + tid];
            msks[tid] = mv;
            const uint32_t bal = __ballot_sync(0xffffffffu, mv != 0);
            if (lane == 0) flgs[wid] = bal;
        }
        __syncthreads();

        // ---- layer 1 (fp32): thread = (point p1, hh-half q1) -> h hi/lo planes ----
        {
            float x[9];
            #pragma unroll
            for (int c = 0; c < 9; ++c) x[c] = xsf[p1 * 9 + c];
            #pragma unroll 4
            for (int i = 0; i < 32; ++i) {
                const int hh = q1 * 64 + 2 * i;
                float a0 = b1s[hh], a1 = b1s[hh + 1];
                #pragma unroll
                for (int c = 0; c < 9; ++c) {
                    a0 = fmaf(x[c], W1s[c * 128 + hh], a0);
                    a1 = fmaf(x[c], W1s[c * 128 + hh + 1], a1);
                }
                a0 = fmaxf(a0, 0.0f);
                a1 = fmaxf(a1, 0.0f);
                uint32_t lo;
                const uint32_t hi = bsplit(a0, a1, lo);
                const uint32_t wv = hword(p1, q1 * 32 + i);
                hhi[wv] = hi;
                hlo[wv] = lo;
            }
        }
        __syncthreads();

        // ---- layer 2: warp (mq, nh), 3-term bf16 mma ----
        const int m00 = msks[mbase + lr] != 0,      m01 = msks[mbase + lr + 8] != 0;
        const int m10 = msks[mbase + 16 + lr] != 0, m11 = msks[mbase + 24 + lr] != 0;

        float acc[2][8][4];
        #pragma unroll
        for (int mi = 0; mi < 2; ++mi)
            #pragma unroll
            for (int nf = 0; nf < 8; ++nf)
                #pragma unroll
                for (int e = 0; e < 4; ++e) acc[mi][nf][e] = 0.0f;

        #pragma unroll 1
        for (int s = 0; s < 8; ++s) {
            uint32_t ah[2][4], al[2][4];
            const int w0 = 8 * s + lc;
            #pragma unroll
            for (int mi = 0; mi < 2; ++mi) {
                const int r0 = mbase + 16 * mi + lr;
                ah[mi][0] = hhi[hword(r0,     w0)];
                ah[mi][1] = hhi[hword(r0 + 8, w0)];
                ah[mi][2] = hhi[hword(r0,     w0 + 4)];
                ah[mi][3] = hhi[hword(r0 + 8, w0 + 4)];
                al[mi][0] = hlo[hword(r0,     w0)];
                al[mi][1] = hlo[hword(r0 + 8, w0)];
                al[mi][2] = hlo[hword(r0,     w0 + 4)];
                al[mi][3] = hlo[hword(r0 + 8, w0 + 4)];
            }
            #pragma unroll
            for (int nf = 0; nf < 8; ++nf) {
                const uint4 B = __ldg(&g_bfrag[(s * 16 + nh * 8 + nf) * 32 + lane]);
                #pragma unroll
                for (int mi = 0; mi < 2; ++mi) {
                    mma16816(acc[mi][nf], ah[mi], B.x, B.y);   // hi*hi
                    mma16816(acc[mi][nf], ah[mi], B.z, B.w);   // hi*lo
                    mma16816(acc[mi][nf], al[mi], B.x, B.y);   // lo*hi
                }
            }
        }

        // ---- epilogue: masked max over the warp's 32 points ----
        #pragma unroll
        for (int nf = 0; nf < 8; ++nf) {
            float e0 = NEG_INF_F, e1 = NEG_INF_F;
            if (m00) { e0 = fmaxf(e0, acc[0][nf][0]); e1 = fmaxf(e1, acc[0][nf][1]); }
            if (m01) { e0 = fmaxf(e0, acc[0][nf][2]); e1 = fmaxf(e1, acc[0][nf][3]); }
            if (m10) { e0 = fmaxf(e0, acc[1][nf][0]); e1 = fmaxf(e1, acc[1][nf][1]); }
            if (m11) { e0 = fmaxf(e0, acc[1][nf][2]); e1 = fmaxf(e1, acc[1][nf][3]); }
            #pragma unroll
            for (int off = 4; off < 32; off <<= 1) {
                e0 = fmaxf(e0, __shfl_xor_sync(0xffffffffu, e0, off));
                e1 = fmaxf(e1, __shfl_xor_sync(0xffffffffu, e1, off));
            }
            if (lane < 4) {
                const int n = nh * 64 + nf * 8 + 2 * lane;
                red[mq * 128 + n]     = e0;
                red[mq * 128 + n + 1] = e1;
            }
        }
        __syncthreads();

        // ---- final: combine 2 M-quads per polyline, +b2, any-valid ----
        {
            const int d = tid & 127, pj = tid >> 7;   // polyline 0/1 of tile
            const float v = fmaxf(red[(2 * pj) * 128 + d],
                                  red[(2 * pj + 1) * 128 + d]);
            const uint32_t av = flgs[2 * pj] | flgs[2 * pj + 1];
            out[((size_t)tile * 2 + pj) * 128 + d] = av ? v + b2s[d] : 0.0f;
        }
    }
}

extern "C" void kernel_launch(void* const* d_in, const int* in_sizes, int n_in,
                              void* d_out, int out_size)
{
    const float* poly = (const float*)d_in[0];
    const int*   mask = (const int*)  d_in[1];
    const float* W1   = (const float*)d_in[2];
    const float* b1   = (const float*)d_in[3];
    const float* W2   = (const float*)d_in[4];
    const float* b2   = (const float*)d_in[5];
    float* out = (float*)d_out;

    const int npoints = in_sizes[0] / 9;           // 1,048,576
    const int ntiles  = npoints / TILE_PTS;        // 8192

    prep_kernel<<<16, 256>>>(W2);

    cudaFuncSetAttribute(poly_mma_kernel,
                         cudaFuncAttributeMaxDynamicSharedMemorySize, SM_BYTES);
    poly_mma_kernel<<<296, NT, SM_BYTES>>>(poly, mask, W1, b1, b2, out, ntiles);
}

// round 7
// speedup vs baseline: 2.4952x; 1.0199x over previous
#include <cuda_runtime.h>
#include <cuda_bf16.h>
#include <stdint.h>

// PolylineEncoder, both layers on bf16 HMMA (mma.sync), 3-term hi/lo split.
// R7: layer 1 moved from FFMA to mma (x@W1, K=16 padded) so ~90% of warp work
// is tensor-pipe; CTA phase overlap no longer gates utilization.

#define NEG_INF_F (-1e9f)
#define NT 256
#define TILE_PTS 128

__device__ __align__(16) uint4 g_bfrag [8 * 16 * 32];   // W2 frags, 64 KB
__device__ __align__(16) uint4 g_w1frag[16 * 32];       // W1 frags, 8 KB

// smem byte offsets
#define SM_XS   0        // 128*9*4 = 4608
#define SM_MSK  4608     // 512
#define SM_FLG  5120     // 64
#define SM_RED  5184     // 2048
#define SM_XHI  7232     // 4096  (128 rows x 8 words)
#define SM_XLO  11328    // 4096
#define SM_HHI  15424    // 32768 (128 rows x 64 words)
#define SM_HLO  48192    // 32768
#define SM_BYTES 80960

// h-plane swizzled word index (row p 0..127, word w 0..63): conflict-free for
// epilogue-1 STS.32 and layer-2 A-frag LDS.32.
__device__ __forceinline__ uint32_t hword(int p, int w) {
    return (uint32_t)(p * 64 + ((w + 4 * (p & 7) + ((p >> 3) & 3)) & 63));
}
// x-plane word index (row p, word w 0..7): 16B-block xor swizzle; conflict-free
// for stager STS.128 and MMA1 A-frag LDS.32.
__device__ __forceinline__ uint32_t xword(int p, int w) {
    return (uint32_t)(p * 8 + (w ^ (((p >> 2) & 1) << 2)));
}

__device__ __forceinline__ void mma16816(float acc[4], const uint32_t a[4],
                                         uint32_t b0, uint32_t b1) {
    asm volatile("mma.sync.aligned.m16n8k16.row.col.f32.bf16.bf16.f32 "
                 "{%0,%1,%2,%3}, {%4,%5,%6,%7}, {%8,%9}, {%0,%1,%2,%3};"
                 : "+f"(acc[0]), "+f"(acc[1]), "+f"(acc[2]), "+f"(acc[3])
                 : "r"(a[0]), "r"(a[1]), "r"(a[2]), "r"(a[3]), "r"(b0), "r"(b1));
}

__device__ __forceinline__ uint32_t bsplit(float v0, float v1, uint32_t& lo) {
    const __nv_bfloat16 h0 = __float2bfloat16(v0), h1 = __float2bfloat16(v1);
    const __nv_bfloat16 l0 = __float2bfloat16(v0 - __bfloat162float(h0));
    const __nv_bfloat16 l1 = __float2bfloat16(v1 - __bfloat162float(h1));
    lo = (uint32_t)__bfloat16_as_ushort(l0) | ((uint32_t)__bfloat16_as_ushort(l1) << 16);
    return (uint32_t)__bfloat16_as_ushort(h0) | ((uint32_t)__bfloat16_as_ushort(h1) << 16);
}

__device__ __forceinline__ uint32_t wpair(const float* W, int k, int n,
                                          uint32_t& lo, int kmax) {
    const float v0 = (k < kmax)     ? W[k * 128 + n]       : 0.0f;
    const float v1 = (k + 1 < kmax) ? W[(k + 1) * 128 + n] : 0.0f;
    return bsplit(v0, v1, lo);
}

// ---- prep: W2 and W1 -> mma B fragments (col-major), hi+lo interleaved ----
__global__ void prep_kernel(const float* __restrict__ W1, const float* __restrict__ W2) {
    const int idx = blockIdx.x * blockDim.x + threadIdx.x;
    if (idx < 8 * 16 * 32) {
        const int lane = idx & 31, nf = (idx >> 5) & 15, s = idx >> 9;
        const int k0 = s * 16 + 2 * (lane & 3);
        const int n  = nf * 8 + (lane >> 2);
        uint32_t l0, l1;
        const uint32_t h0 = wpair(W2, k0,     n, l0, 128);
        const uint32_t h1 = wpair(W2, k0 + 8, n, l1, 128);
        g_bfrag[idx] = make_uint4(h0, h1, l0, l1);
    }
    if (idx < 16 * 32) {
        const int lane = idx & 31, nf = idx >> 5;
        const int k0 = 2 * (lane & 3);
        const int n  = nf * 8 + (lane >> 2);
        uint32_t l0, l1;
        const uint32_t h0 = wpair(W1, k0,     n, l0, 9);
        const uint32_t h1 = wpair(W1, k0 + 8, n, l1, 9);
        g_w1frag[idx] = make_uint4(h0, h1, l0, l1);
    }
}

extern __shared__ unsigned char smB[];

__global__ void __launch_bounds__(NT, 2)
poly_mma_kernel(const float* __restrict__ poly, const int* __restrict__ mask,
                const float* __restrict__ b1g, const float* __restrict__ b2g,
                float* __restrict__ out, int ntiles)
{
    const int tid = threadIdx.x, wid = tid >> 5, lane = tid & 31;
    float* xsf = (float*)(smB + SM_XS);
    int*   msks = (int*)(smB + SM_MSK);
    uint32_t* flgs = (uint32_t*)(smB + SM_FLG);
    float* red = (float*)(smB + SM_RED);
    uint32_t* xhi = (uint32_t*)(smB + SM_XHI);
    uint32_t* xlo = (uint32_t*)(smB + SM_XLO);
    uint32_t* hhi = (uint32_t*)(smB + SM_HHI);
    uint32_t* hlo = (uint32_t*)(smB + SM_HLO);

    const int lr = lane >> 2, lc = lane & 3;    // fragment lane coords
    const int mq = wid & 3, nh = wid >> 2;      // warp = (M-quad, N-half)
    const int mbase = 32 * mq;

    // per-thread b1 pairs for MMA1 epilogue: b1r[2nf+j] = b1[nh*64+nf*8+2lc+j]
    float b1r[16];
    #pragma unroll
    for (int nf = 0; nf < 8; ++nf) {
        b1r[2 * nf]     = b1g[nh * 64 + nf * 8 + 2 * lc];
        b1r[2 * nf + 1] = b1g[nh * 64 + nf * 8 + 2 * lc + 1];
    }

    for (int tile = blockIdx.x; tile < ntiles; tile += gridDim.x) {
        __syncthreads();

        // ---- stage x (float) + mask ----
        const float* xg = poly + (size_t)tile * (TILE_PTS * 9);
        #pragma unroll
        for (int i = tid; i < TILE_PTS * 9; i += NT) xsf[i] = xg[i];
        if (tid < TILE_PTS) {
            const int mv = mask[(size_t)tile * TILE_PTS + tid];
            msks[tid] = mv;
            const uint32_t bal = __ballot_sync(0xffffffffu, mv != 0);
            if (lane == 0) flgs[wid] = bal;
        }
        __syncthreads();

        // ---- build x bf16 hi/lo A-planes (thread = row p, k-half hf) ----
        {
            const int p = tid >> 1, hf = tid & 1;
            uint32_t hiw[4] = {0, 0, 0, 0}, low[4] = {0, 0, 0, 0};
            if (hf == 0) {
                #pragma unroll
                for (int j = 0; j < 4; ++j)
                    hiw[j] = bsplit(xsf[p * 9 + 2 * j], xsf[p * 9 + 2 * j + 1], low[j]);
            } else {
                hiw[0] = bsplit(xsf[p * 9 + 8], 0.0f, low[0]);
            }
            const int blk = hf ^ ((p >> 2) & 1);
            *(uint4*)(xhi + p * 8 + blk * 4) = make_uint4(hiw[0], hiw[1], hiw[2], hiw[3]);
            *(uint4*)(xlo + p * 8 + blk * 4) = make_uint4(low[0], low[1], low[2], low[3]);
        }
        __syncthreads();

        float acc[2][8][4];

        // ---- MMA1: h = x @ W1 (K=16, 3-term) ----
        {
            uint32_t xah[2][4], xal[2][4];
            #pragma unroll
            for (int mi = 0; mi < 2; ++mi) {
                const int rA = mbase + 16 * mi + lr, rB = rA + 8;
                xah[mi][0] = xhi[xword(rA, lc)];
                xah[mi][1] = xhi[xword(rB, lc)];
                xah[mi][2] = xhi[xword(rA, lc + 4)];
                xah[mi][3] = xhi[xword(rB, lc + 4)];
                xal[mi][0] = xlo[xword(rA, lc)];
                xal[mi][1] = xlo[xword(rB, lc)];
                xal[mi][2] = xlo[xword(rA, lc + 4)];
                xal[mi][3] = xlo[xword(rB, lc + 4)];
            }
            #pragma unroll
            for (int mi = 0; mi < 2; ++mi)
                #pragma unroll
                for (int nf = 0; nf < 8; ++nf)
                    #pragma unroll
                    for (int e = 0; e < 4; ++e) acc[mi][nf][e] = 0.0f;
            #pragma unroll
            for (int nf = 0; nf < 8; ++nf) {
                const uint4 B = __ldg(&g_w1frag[(nh * 8 + nf) * 32 + lane]);
                #pragma unroll
                for (int mi = 0; mi < 2; ++mi) {
                    mma16816(acc[mi][nf], xah[mi], B.x, B.y);
                    mma16816(acc[mi][nf], xah[mi], B.z, B.w);
                    mma16816(acc[mi][nf], xal[mi], B.x, B.y);
                }
            }
            // epilogue-1: +b1, relu, split -> h planes
            #pragma unroll
            for (int nf = 0; nf < 8; ++nf) {
                const int w = nh * 32 + nf * 4 + lc;
                #pragma unroll
                for (int mi = 0; mi < 2; ++mi) {
                    const int r = mbase + 16 * mi + lr;
                    const float e0 = fmaxf(acc[mi][nf][0] + b1r[2 * nf],     0.0f);
                    const float e1 = fmaxf(acc[mi][nf][1] + b1r[2 * nf + 1], 0.0f);
                    const float e2 = fmaxf(acc[mi][nf][2] + b1r[2 * nf],     0.0f);
                    const float e3 = fmaxf(acc[mi][nf][3] + b1r[2 * nf + 1], 0.0f);
                    uint32_t lo0, lo1;
                    const uint32_t hi0 = bsplit(e0, e1, lo0);
                    const uint32_t hi1 = bsplit(e2, e3, lo1);
                    hhi[hword(r, w)] = hi0;      hlo[hword(r, w)] = lo0;
                    hhi[hword(r + 8, w)] = hi1;  hlo[hword(r + 8, w)] = lo1;
                }
            }
        }
        __syncthreads();

        // ---- MMA2: feat = h @ W2 (K=128, 3-term) ----
        const int m00 = msks[mbase + lr] != 0,      m01 = msks[mbase + lr + 8] != 0;
        const int m10 = msks[mbase + 16 + lr] != 0, m11 = msks[mbase + 24 + lr] != 0;

        #pragma unroll
        for (int mi = 0; mi < 2; ++mi)
            #pragma unroll
            for (int nf = 0; nf < 8; ++nf)
                #pragma unroll
                for (int e = 0; e < 4; ++e) acc[mi][nf][e] = 0.0f;

        #pragma unroll 1
        for (int s = 0; s < 8; ++s) {
            uint32_t ah[2][4], al[2][4];
            const int w0 = 8 * s + lc;
            #pragma unroll
            for (int mi = 0; mi < 2; ++mi) {
                const int r0 = mbase + 16 * mi + lr;
                ah[mi][0] = hhi[hword(r0,     w0)];
                ah[mi][1] = hhi[hword(r0 + 8, w0)];
                ah[mi][2] = hhi[hword(r0,     w0 + 4)];
                ah[mi][3] = hhi[hword(r0 + 8, w0 + 4)];
                al[mi][0] = hlo[hword(r0,     w0)];
                al[mi][1] = hlo[hword(r0 + 8, w0)];
                al[mi][2] = hlo[hword(r0,     w0 + 4)];
                al[mi][3] = hlo[hword(r0 + 8, w0 + 4)];
            }
            #pragma unroll
            for (int nf = 0; nf < 8; ++nf) {
                const uint4 B = __ldg(&g_bfrag[(s * 16 + nh * 8 + nf) * 32 + lane]);
                #pragma unroll
                for (int mi = 0; mi < 2; ++mi) {
                    mma16816(acc[mi][nf], ah[mi], B.x, B.y);
                    mma16816(acc[mi][nf], ah[mi], B.z, B.w);
                    mma16816(acc[mi][nf], al[mi], B.x, B.y);
                }
            }
        }

        // ---- epilogue-2: masked max over the warp's 32 points ----
        #pragma unroll
        for (int nf = 0; nf < 8; ++nf) {
            float e0 = NEG_INF_F, e1 = NEG_INF_F;
            if (m00) { e0 = fmaxf(e0, acc[0][nf][0]); e1 = fmaxf(e1, acc[0][nf][1]); }
            if (m01) { e0 = fmaxf(e0, acc[0][nf][2]); e1 = fmaxf(e1, acc[0][nf][3]); }
            if (m10) { e0 = fmaxf(e0, acc[1][nf][0]); e1 = fmaxf(e1, acc[1][nf][1]); }
            if (m11) { e0 = fmaxf(e0, acc[1][nf][2]); e1 = fmaxf(e1, acc[1][nf][3]); }
            #pragma unroll
            for (int off = 4; off < 32; off <<= 1) {
                e0 = fmaxf(e0, __shfl_xor_sync(0xffffffffu, e0, off));
                e1 = fmaxf(e1, __shfl_xor_sync(0xffffffffu, e1, off));
            }
            if (lane < 4) {
                const int n = nh * 64 + nf * 8 + 2 * lane;
                red[mq * 128 + n]     = e0;
                red[mq * 128 + n + 1] = e1;
            }
        }
        __syncthreads();

        // ---- final: combine 2 M-quads per polyline, +b2, any-valid ----
        {
            const int d = tid & 127, pj = tid >> 7;
            const float v = fmaxf(red[(2 * pj) * 128 + d],
                                  red[(2 * pj + 1) * 128 + d]);
            const uint32_t av = flgs[2 * pj] | flgs[2 * pj + 1];
            out[((size_t)tile * 2 + pj) * 128 + d] = av ? v + b2g[d] : 0.0f;
        }
    }
}

extern "C" void kernel_launch(void* const* d_in, const int* in_sizes, int n_in,
                              void* d_out, int out_size)
{
    const float* poly = (const float*)d_in[0];
    const int*   mask = (const int*)  d_in[1];
    const float* W1   = (const float*)d_in[2];
    const float* b1   = (const float*)d_in[3];
    const float* W2   = (const float*)d_in[4];
    const float* b2   = (const float*)d_in[5];
    float* out = (float*)d_out;

    const int npoints = in_sizes[0] / 9;           // 1,048,576
    const int ntiles  = npoints / TILE_PTS;        // 8192

    prep_kernel<<<16, 256>>>(W1, W2);

    cudaFuncSetAttribute(poly_mma_kernel,
                         cudaFuncAttributeMaxDynamicSharedMemorySize, SM_BYTES);
    poly_mma_kernel<<<296, NT, SM_BYTES>>>(poly, mask, b1, b2, out, ntiles);
}

// round 8
// speedup vs baseline: 2.8057x; 1.1244x over previous
#include <cuda_runtime.h>
#include <cuda_bf16.h>
#include <stdint.h>

// PolylineEncoder, both layers on bf16 HMMA (mma.sync), 3-term hi/lo split.
// R8: 64-pt tiles, warp = (M-quad, N-quarter) -> acc 32 regs, smem 40.5 KB,
// launch_bounds(256,3) -> 3 CTAs/SM (24 warps) to cover latency; ldmatrix.x4
// replaces scalar LDS for A fragments.

#define NEG_INF_F (-1e9f)
#define NT 256
#define TILE_PTS 64

__device__ __align__(16) uint4 g_bfrag [8 * 16 * 32];   // W2 frags, 64 KB (L1)
__device__ __align__(16) uint4 g_w1frag[16 * 32];       // W1 frags, 8 KB (L1)

// smem byte offsets (total 40512)
#define SM_XS   0        // 64*9*4 = 2304
#define SM_MSK  2304     // 256
#define SM_FLG  2560     // 64
#define SM_RED  2624     // 2*128*4 = 1024
#define SM_XHI  3648     // 64*8*4 = 2048
#define SM_XLO  5696     // 2048
#define SM_HHI  7744     // 64*64*4 = 16384
#define SM_HLO  24128    // 16384
#define SM_BYTES 40512

// h-plane word index (row p 0..63, word w 0..63), rot by 4-word units only so
// 16B blocks stay contiguous (ldmatrix-compatible). Conflict-free for
// epi-1 STS.32 (banks 4lr+lc) and ldmatrix phases (8 distinct bank quads).
__device__ __forceinline__ uint32_t hword(int p, int w) {
    return (uint32_t)(p * 64 + ((w + 4 * (p & 7)) & 63));
}
// x-plane word index (row p, word w in {0,4} blocks): 16B xor swizzle.
__device__ __forceinline__ uint32_t xblk(int p, int wb) {
    return (uint32_t)(p * 8 + ((wb >> 2) ^ ((p >> 2) & 1)) * 4);
}

__device__ __forceinline__ void ldm4(uint32_t r[4], uint32_t addr) {
    asm volatile("ldmatrix.sync.aligned.m8n8.x4.shared.b16 {%0,%1,%2,%3}, [%4];"
                 : "=r"(r[0]), "=r"(r[1]), "=r"(r[2]), "=r"(r[3]) : "r"(addr));
}

__device__ __forceinline__ void mma16816(float acc[4], const uint32_t a[4],
                                         uint32_t b0, uint32_t b1) {
    asm volatile("mma.sync.aligned.m16n8k16.row.col.f32.bf16.bf16.f32 "
                 "{%0,%1,%2,%3}, {%4,%5,%6,%7}, {%8,%9}, {%0,%1,%2,%3};"
                 : "+f"(acc[0]), "+f"(acc[1]), "+f"(acc[2]), "+f"(acc[3])
                 : "r"(a[0]), "r"(a[1]), "r"(a[2]), "r"(a[3]), "r"(b0), "r"(b1));
}

__device__ __forceinline__ uint32_t bsplit(float v0, float v1, uint32_t& lo) {
    const __nv_bfloat16 h0 = __float2bfloat16(v0), h1 = __float2bfloat16(v1);
    const __nv_bfloat16 l0 = __float2bfloat16(v0 - __bfloat162float(h0));
    const __nv_bfloat16 l1 = __float2bfloat16(v1 - __bfloat162float(h1));
    lo = (uint32_t)__bfloat16_as_ushort(l0) | ((uint32_t)__bfloat16_as_ushort(l1) << 16);
    return (uint32_t)__bfloat16_as_ushort(h0) | ((uint32_t)__bfloat16_as_ushort(h1) << 16);
}

__device__ __forceinline__ uint32_t wpair(const float* W, int k, int n,
                                          uint32_t& lo, int kmax) {
    const float v0 = (k < kmax)     ? W[k * 128 + n]       : 0.0f;
    const float v1 = (k + 1 < kmax) ? W[(k + 1) * 128 + n] : 0.0f;
    return bsplit(v0, v1, lo);
}

// ---- prep: W2 and W1 -> mma B fragments (col-major), hi+lo interleaved ----
__global__ void prep_kernel(const float* __restrict__ W1, const float* __restrict__ W2) {
    const int idx = blockIdx.x * blockDim.x + threadIdx.x;
    if (idx < 8 * 16 * 32) {
        const int lane = idx & 31, nf = (idx >> 5) & 15, s = idx >> 9;
        const int k0 = s * 16 + 2 * (lane & 3);
        const int n  = nf * 8 + (lane >> 2);
        uint32_t l0, l1;
        const uint32_t h0 = wpair(W2, k0,     n, l0, 128);
        const uint32_t h1 = wpair(W2, k0 + 8, n, l1, 128);
        g_bfrag[idx] = make_uint4(h0, h1, l0, l1);
    }
    if (idx < 16 * 32) {
        const int lane = idx & 31, nf = idx >> 5;
        const int k0 = 2 * (lane & 3);
        const int n  = nf * 8 + (lane >> 2);
        uint32_t l0, l1;
        const uint32_t h0 = wpair(W1, k0,     n, l0, 9);
        const uint32_t h1 = wpair(W1, k0 + 8, n, l1, 9);
        g_w1frag[idx] = make_uint4(h0, h1, l0, l1);
    }
}

extern __shared__ unsigned char smB[];

__global__ void __launch_bounds__(NT, 3)
poly_mma_kernel(const float* __restrict__ poly, const int* __restrict__ mask,
                const float* __restrict__ b1g, const float* __restrict__ b2g,
                float* __restrict__ out, int ntiles)
{
    const int tid = threadIdx.x, wid = tid >> 5, lane = tid & 31;
    float* xsf = (float*)(smB + SM_XS);
    int*   msks = (int*)(smB + SM_MSK);
    uint32_t* flgs = (uint32_t*)(smB + SM_FLG);
    float* red = (float*)(smB + SM_RED);

    uint32_t sb;
    asm("{ .reg .u64 t; cvta.to.shared.u64 t, %1; cvt.u32.u64 %0, t; }"
        : "=r"(sb) : "l"(smB));

    const int lr = lane >> 2, lc = lane & 3;    // fragment lane coords
    const int mq = wid & 1, nq = wid >> 1;      // warp = (M-quad, N-quarter)
    const int mbase = 32 * mq;

    // per-thread b1 pairs: b1r[2nf+j] = b1[nq*32 + nf*8 + 2lc + j]
    float b1r[8];
    #pragma unroll
    for (int nf = 0; nf < 4; ++nf) {
        b1r[2 * nf]     = b1g[nq * 32 + nf * 8 + 2 * lc];
        b1r[2 * nf + 1] = b1g[nq * 32 + nf * 8 + 2 * lc + 1];
    }

    // ldmatrix lane-address components
    const int lsub = lane >> 3;                 // 0..3: (rowblk, kblk)
    const int lrow = (lsub & 1) * 8 + (lane & 7);
    const int lkb  = (lsub >> 1) * 4;

    for (int tile = blockIdx.x; tile < ntiles; tile += gridDim.x) {
        __syncthreads();

        // ---- stage x (float) + mask (tile = 1 polyline, 64 pts) ----
        const float* xg = poly + (size_t)tile * (TILE_PTS * 9);
        #pragma unroll
        for (int i = tid; i < TILE_PTS * 9; i += NT) xsf[i] = xg[i];
        if (tid < TILE_PTS) {
            const int mv = mask[(size_t)tile * TILE_PTS + tid];
            msks[tid] = mv;
            const uint32_t bal = __ballot_sync(0xffffffffu, mv != 0);
            if (lane == 0) flgs[wid] = bal;
        }
        __syncthreads();

        // ---- build x bf16 hi/lo A-planes (thread = row p, k-half hf) ----
        if (tid < 128) {
            const int p = tid >> 1, hf = tid & 1;
            uint32_t hiw[4] = {0, 0, 0, 0}, low[4] = {0, 0, 0, 0};
            if (hf == 0) {
                #pragma unroll
                for (int j = 0; j < 4; ++j)
                    hiw[j] = bsplit(xsf[p * 9 + 2 * j], xsf[p * 9 + 2 * j + 1], low[j]);
            } else {
                hiw[0] = bsplit(xsf[p * 9 + 8], 0.0f, low[0]);
            }
            const uint32_t wv = xblk(p, hf * 4);
            *(uint4*)(smB + SM_XHI + 4 * wv) = make_uint4(hiw[0], hiw[1], hiw[2], hiw[3]);
            *(uint4*)(smB + SM_XLO + 4 * wv) = make_uint4(low[0], low[1], low[2], low[3]);
        }
        __syncthreads();

        float acc[2][4][4];

        // ---- MMA1: h = x @ W1 (K=16, 3-term) ----
        {
            uint32_t xah[2][4], xal[2][4];
            #pragma unroll
            for (int mi = 0; mi < 2; ++mi) {
                const int r = mbase + 16 * mi + lrow;
                ldm4(xah[mi], sb + SM_XHI + 4 * xblk(r, lkb));
                ldm4(xal[mi], sb + SM_XLO + 4 * xblk(r, lkb));
            }
            #pragma unroll
            for (int mi = 0; mi < 2; ++mi)
                #pragma unroll
                for (int nf = 0; nf < 4; ++nf)
                    #pragma unroll
                    for (int e = 0; e < 4; ++e) acc[mi][nf][e] = 0.0f;
            #pragma unroll
            for (int nf = 0; nf < 4; ++nf) {
                const uint4 B = __ldg(&g_w1frag[(nq * 4 + nf) * 32 + lane]);
                #pragma unroll
                for (int mi = 0; mi < 2; ++mi) {
                    mma16816(acc[mi][nf], xah[mi], B.x, B.y);
                    mma16816(acc[mi][nf], xah[mi], B.z, B.w);
                    mma16816(acc[mi][nf], xal[mi], B.x, B.y);
                }
            }
            // epilogue-1: +b1, relu, split -> h planes
            #pragma unroll
            for (int nf = 0; nf < 4; ++nf) {
                const int w = nq * 16 + nf * 4 + lc;
                #pragma unroll
                for (int mi = 0; mi < 2; ++mi) {
                    const int r = mbase + 16 * mi + lr;
                    const float e0 = fmaxf(acc[mi][nf][0] + b1r[2 * nf],     0.0f);
                    const float e1 = fmaxf(acc[mi][nf][1] + b1r[2 * nf + 1], 0.0f);
                    const float e2 = fmaxf(acc[mi][nf][2] + b1r[2 * nf],     0.0f);
                    const float e3 = fmaxf(acc[mi][nf][3] + b1r[2 * nf + 1], 0.0f);
                    uint32_t lo0, lo1;
                    const uint32_t hi0 = bsplit(e0, e1, lo0);
                    const uint32_t hi1 = bsplit(e2, e3, lo1);
                    *(uint32_t*)(smB + SM_HHI + 4 * hword(r, w))     = hi0;
                    *(uint32_t*)(smB + SM_HLO + 4 * hword(r, w))     = lo0;
                    *(uint32_t*)(smB + SM_HHI + 4 * hword(r + 8, w)) = hi1;
                    *(uint32_t*)(smB + SM_HLO + 4 * hword(r + 8, w)) = lo1;
                }
            }
        }
        __syncthreads();

        // ---- MMA2: feat = h @ W2 (K=128, 3-term) ----
        const int m00 = msks[mbase + lr] != 0,      const_m01 = msks[mbase + lr + 8] != 0;
        const int m10 = msks[mbase + 16 + lr] != 0, m11 = msks[mbase + 24 + lr] != 0;
        const int m01 = const_m01;

        #pragma unroll
        for (int mi = 0; mi < 2; ++mi)
            #pragma unroll
            for (int nf = 0; nf < 4; ++nf)
                #pragma unroll
                for (int e = 0; e < 4; ++e) acc[mi][nf][e] = 0.0f;

        #pragma unroll 1
        for (int s = 0; s < 8; ++s) {
            uint32_t ah[2][4], al[2][4];
            const int w0 = 8 * s + lkb;
            #pragma unroll
            for (int mi = 0; mi < 2; ++mi) {
                const int r = mbase + 16 * mi + lrow;
                ldm4(ah[mi], sb + SM_HHI + 4 * hword(r, w0));
                ldm4(al[mi], sb + SM_HLO + 4 * hword(r, w0));
            }
            #pragma unroll
            for (int nf = 0; nf < 4; ++nf) {
                const uint4 B = __ldg(&g_bfrag[(s * 16 + nq * 4 + nf) * 32 + lane]);
                #pragma unroll
                for (int mi = 0; mi < 2; ++mi) {
                    mma16816(acc[mi][nf], ah[mi], B.x, B.y);
                    mma16816(acc[mi][nf], ah[mi], B.z, B.w);
                    mma16816(acc[mi][nf], al[mi], B.x, B.y);
                }
            }
        }

        // ---- epilogue-2: masked max over the warp's 32 points ----
        #pragma unroll
        for (int nf = 0; nf < 4; ++nf) {
            float e0 = NEG_INF_F, e1 = NEG_INF_F;
            if (m00) { e0 = fmaxf(e0, acc[0][nf][0]); e1 = fmaxf(e1, acc[0][nf][1]); }
            if (m01) { e0 = fmaxf(e0, acc[0][nf][2]); e1 = fmaxf(e1, acc[0][nf][3]); }
            if (m10) { e0 = fmaxf(e0, acc[1][nf][0]); e1 = fmaxf(e1, acc[1][nf][1]); }
            if (m11) { e0 = fmaxf(e0, acc[1][nf][2]); e1 = fmaxf(e1, acc[1][nf][3]); }
            #pragma unroll
            for (int off = 4; off < 32; off <<= 1) {
                e0 = fmaxf(e0, __shfl_xor_sync(0xffffffffu, e0, off));
                e1 = fmaxf(e1, __shfl_xor_sync(0xffffffffu, e1, off));
            }
            if (lane < 4) {
                const int n = nq * 32 + nf * 8 + 2 * lane;
                red[mq * 128 + n]     = e0;
                red[mq * 128 + n + 1] = e1;
            }
        }
        __syncthreads();

        // ---- final: combine 2 M-quads, +b2, any-valid; 1 polyline/tile ----
        if (tid < 128) {
            const float v = fmaxf(red[tid], red[128 + tid]);
            const uint32_t av = flgs[0] | flgs[1];
            out[(size_t)tile * 128 + tid] = av ? v + b2g[tid] : 0.0f;
        }
    }
}

extern "C" void kernel_launch(void* const* d_in, const int* in_sizes, int n_in,
                              void* d_out, int out_size)
{
    const float* poly = (const float*)d_in[0];
    const int*   mask = (const int*)  d_in[1];
    const float* W1   = (const float*)d_in[2];
    const float* b1   = (const float*)d_in[3];
    const float* W2   = (const float*)d_in[4];
    const float* b2   = (const float*)d_in[5];
    float* out = (float*)d_out;

    const int npoints = in_sizes[0] / 9;           // 1,048,576
    const int ntiles  = npoints / TILE_PTS;        // 16384

    prep_kernel<<<16, 256>>>(W1, W2);

    cudaFuncSetAttribute(poly_mma_kernel,
                         cudaFuncAttributeMaxDynamicSharedMemorySize, SM_BYTES);
    poly_mma_kernel<<<444, NT, SM_BYTES>>>(poly, mask, b1, b2, out, ntiles);
}

// round 9
// speedup vs baseline: 2.8801x; 1.0265x over previous
#include <cuda_runtime.h>
#include <cuda_bf16.h>
#include <stdint.h>

// PolylineEncoder, both layers on bf16 HMMA (mma.sync), 3-term hi/lo split.
// R9: cp.async double-buffered x/mask staging (prefetch next tile during
// compute), MMA1 A-fragments built in registers (x-plane smem + 1 barrier
// removed). 3 CTAs/SM, 24 warps.

#define NEG_INF_F (-1e9f)
#define NT 256
#define TILE_PTS 64

__device__ __align__(16) uint4 g_bfrag [8 * 16 * 32];   // W2 frags, 64 KB (L1)
__device__ __align__(16) uint4 g_w1frag[16 * 32];       // W1 frags, 8 KB (L1)

// smem byte offsets
#define SM_STG   0        // 2 bufs x (2304 x + 256 mask)
#define STG_STRIDE 2560
#define SM_FLG   5120     // 64
#define SM_RED   5184     // 1024
#define SM_HHI   6208     // 64*64*4 = 16384
#define SM_HLO   22592    // 16384
#define SM_BYTES 38976

// h-plane word index (row p 0..63, word w 0..63), 4-word rotation: 16B blocks
// contiguous (ldmatrix-compatible); conflict-free for epi-1 STS.32 and
// ldmatrix read phases.
__device__ __forceinline__ uint32_t hword(int p, int w) {
    return (uint32_t)(p * 64 + ((w + 4 * (p & 7)) & 63));
}

__device__ __forceinline__ void ldm4(uint32_t r[4], uint32_t addr) {
    asm volatile("ldmatrix.sync.aligned.m8n8.x4.shared.b16 {%0,%1,%2,%3}, [%4];"
                 : "=r"(r[0]), "=r"(r[1]), "=r"(r[2]), "=r"(r[3]) : "r"(addr));
}

__device__ __forceinline__ void mma16816(float acc[4], const uint32_t a[4],
                                         uint32_t b0, uint32_t b1) {
    asm volatile("mma.sync.aligned.m16n8k16.row.col.f32.bf16.bf16.f32 "
                 "{%0,%1,%2,%3}, {%4,%5,%6,%7}, {%8,%9}, {%0,%1,%2,%3};"
                 : "+f"(acc[0]), "+f"(acc[1]), "+f"(acc[2]), "+f"(acc[3])
                 : "r"(a[0]), "r"(a[1]), "r"(a[2]), "r"(a[3]), "r"(b0), "r"(b1));
}

__device__ __forceinline__ uint32_t bsplit(float v0, float v1, uint32_t& lo) {
    const __nv_bfloat16 h0 = __float2bfloat16(v0), h1 = __float2bfloat16(v1);
    const __nv_bfloat16 l0 = __float2bfloat16(v0 - __bfloat162float(h0));
    const __nv_bfloat16 l1 = __float2bfloat16(v1 - __bfloat162float(h1));
    lo = (uint32_t)__bfloat16_as_ushort(l0) | ((uint32_t)__bfloat16_as_ushort(l1) << 16);
    return (uint32_t)__bfloat16_as_ushort(h0) | ((uint32_t)__bfloat16_as_ushort(h1) << 16);
}

__device__ __forceinline__ uint32_t wpair(const float* W, int k, int n,
                                          uint32_t& lo, int kmax) {
    const float v0 = (k < kmax)     ? W[k * 128 + n]       : 0.0f;
    const float v1 = (k + 1 < kmax) ? W[(k + 1) * 128 + n] : 0.0f;
    return bsplit(v0, v1, lo);
}

__device__ __forceinline__ void cp16(uint32_t dst, const void* src) {
    asm volatile("cp.async.cg.shared.global [%0], [%1], 16;" :: "r"(dst), "l"(src));
}
#define CP_COMMIT() asm volatile("cp.async.commit_group;" ::: "memory")
#define CP_WAIT1()  asm volatile("cp.async.wait_group 1;" ::: "memory")

// ---- prep: W2 and W1 -> mma B fragments (col-major), hi+lo interleaved ----
__global__ void prep_kernel(const float* __restrict__ W1, const float* __restrict__ W2) {
    const int idx = blockIdx.x * blockDim.x + threadIdx.x;
    if (idx < 8 * 16 * 32) {
        const int lane = idx & 31, nf = (idx >> 5) & 15, s = idx >> 9;
        const int k0 = s * 16 + 2 * (lane & 3);
        const int n  = nf * 8 + (lane >> 2);
        uint32_t l0, l1;
        const uint32_t h0 = wpair(W2, k0,     n, l0, 128);
        const uint32_t h1 = wpair(W2, k0 + 8, n, l1, 128);
        g_bfrag[idx] = make_uint4(h0, h1, l0, l1);
    }
    if (idx < 16 * 32) {
        const int lane = idx & 31, nf = idx >> 5;
        const int k0 = 2 * (lane & 3);
        const int n  = nf * 8 + (lane >> 2);
        uint32_t l0, l1;
        const uint32_t h0 = wpair(W1, k0,     n, l0, 9);
        const uint32_t h1 = wpair(W1, k0 + 8, n, l1, 9);
        g_w1frag[idx] = make_uint4(h0, h1, l0, l1);
    }
}

extern __shared__ unsigned char smB[];

__device__ __forceinline__ void stage_tile(uint32_t sb, int buf,
                                           const float* poly, const int* mask,
                                           int tile, int tid) {
    const uint32_t dst = sb + SM_STG + (uint32_t)buf * STG_STRIDE;
    if (tid < 144)
        cp16(dst + tid * 16, (const char*)poly + (size_t)tile * 2304 + tid * 16);
    else if (tid < 160)
        cp16(dst + 2304 + (tid - 144) * 16,
             (const char*)mask + (size_t)tile * 256 + (tid - 144) * 16);
}

__global__ void __launch_bounds__(NT, 3)
poly_mma_kernel(const float* __restrict__ poly, const int* __restrict__ mask,
                const float* __restrict__ b1g, const float* __restrict__ b2g,
                float* __restrict__ out, int ntiles)
{
    const int tid = threadIdx.x, wid = tid >> 5, lane = tid & 31;
    uint32_t* flgs = (uint32_t*)(smB + SM_FLG);
    float* red = (float*)(smB + SM_RED);

    uint32_t sb;
    asm("{ .reg .u64 t; cvta.to.shared.u64 t, %1; cvt.u32.u64 %0, t; }"
        : "=r"(sb) : "l"(smB));

    const int lr = lane >> 2, lc = lane & 3;    // fragment lane coords
    const int mq = wid & 1, nq = wid >> 1;      // warp = (M-quad, N-quarter)
    const int mbase = 32 * mq;

    // per-thread b1 pairs: b1r[2nf+j] = b1[nq*32 + nf*8 + 2lc + j]
    float b1r[8];
    #pragma unroll
    for (int nf = 0; nf < 4; ++nf) {
        b1r[2 * nf]     = b1g[nq * 32 + nf * 8 + 2 * lc];
        b1r[2 * nf + 1] = b1g[nq * 32 + nf * 8 + 2 * lc + 1];
    }

    // ldmatrix lane-address components
    const int lsub = lane >> 3;
    const int lrow = (lsub & 1) * 8 + (lane & 7);
    const int lkb  = (lsub >> 1) * 4;

    // prologue: prefetch first tile into buf 0
    int buf = 0;
    if (blockIdx.x < ntiles) stage_tile(sb, 0, poly, mask, blockIdx.x, tid);
    CP_COMMIT();

    for (int tile = blockIdx.x; tile < ntiles; tile += gridDim.x) {
        // prefetch next tile into the other buffer (clamped; harmless refetch)
        const int tn = tile + gridDim.x;
        stage_tile(sb, buf ^ 1, poly, mask, (tn < ntiles) ? tn : tile, tid);
        CP_COMMIT();
        CP_WAIT1();            // current buf's group complete
        __syncthreads();       // bar #1

        const float* xs  = (const float*)(smB + SM_STG + (uint32_t)buf * STG_STRIDE);
        const int* msks  = (const int*)(smB + SM_STG + (uint32_t)buf * STG_STRIDE + 2304);

        // flags: any-valid ballots (warps 0,1 cover the 64 points)
        if (tid < TILE_PTS) {
            const uint32_t bal = __ballot_sync(0xffffffffu, msks[tid] != 0);
            if (lane == 0) flgs[wid] = bal;
        }

        float acc[2][4][4];

        // ---- MMA1: h = x @ W1 (K=16, 3-term); A built in registers ----
        {
            uint32_t xah[2][4], xal[2][4];
            #pragma unroll
            for (int mi = 0; mi < 2; ++mi) {
                const int rA = mbase + 16 * mi + lr, rB = rA + 8;
                xah[mi][0] = bsplit(xs[rA * 9 + 2 * lc], xs[rA * 9 + 2 * lc + 1], xal[mi][0]);
                xah[mi][1] = bsplit(xs[rB * 9 + 2 * lc], xs[rB * 9 + 2 * lc + 1], xal[mi][1]);
                if (lc == 0) {
                    xah[mi][2] = bsplit(xs[rA * 9 + 8], 0.0f, xal[mi][2]);
                    xah[mi][3] = bsplit(xs[rB * 9 + 8], 0.0f, xal[mi][3]);
                } else {
                    xah[mi][2] = 0; xah[mi][3] = 0; xal[mi][2] = 0; xal[mi][3] = 0;
                }
            }
            #pragma unroll
            for (int mi = 0; mi < 2; ++mi)
                #pragma unroll
                for (int nf = 0; nf < 4; ++nf)
                    #pragma unroll
                    for (int e = 0; e < 4; ++e) acc[mi][nf][e] = 0.0f;
            #pragma unroll
            for (int nf = 0; nf < 4; ++nf) {
                const uint4 B = __ldg(&g_w1frag[(nq * 4 + nf) * 32 + lane]);
                #pragma unroll
                for (int mi = 0; mi < 2; ++mi) {
                    mma16816(acc[mi][nf], xah[mi], B.x, B.y);
                    mma16816(acc[mi][nf], xah[mi], B.z, B.w);
                    mma16816(acc[mi][nf], xal[mi], B.x, B.y);
                }
            }
            // epilogue-1: +b1, relu, split -> h planes
            #pragma unroll
            for (int nf = 0; nf < 4; ++nf) {
                const int w = nq * 16 + nf * 4 + lc;
                #pragma unroll
                for (int mi = 0; mi < 2; ++mi) {
                    const int r = mbase + 16 * mi + lr;
                    const float e0 = fmaxf(acc[mi][nf][0] + b1r[2 * nf],     0.0f);
                    const float e1 = fmaxf(acc[mi][nf][1] + b1r[2 * nf + 1], 0.0f);
                    const float e2 = fmaxf(acc[mi][nf][2] + b1r[2 * nf],     0.0f);
                    const float e3 = fmaxf(acc[mi][nf][3] + b1r[2 * nf + 1], 0.0f);
                    uint32_t lo0, lo1;
                    const uint32_t hi0 = bsplit(e0, e1, lo0);
                    const uint32_t hi1 = bsplit(e2, e3, lo1);
                    *(uint32_t*)(smB + SM_HHI + 4 * hword(r, w))     = hi0;
                    *(uint32_t*)(smB + SM_HLO + 4 * hword(r, w))     = lo0;
                    *(uint32_t*)(smB + SM_HHI + 4 * hword(r + 8, w)) = hi1;
                    *(uint32_t*)(smB + SM_HLO + 4 * hword(r + 8, w)) = lo1;
                }
            }
        }
        __syncthreads();       // bar #2

        // ---- MMA2: feat = h @ W2 (K=128, 3-term) ----
        const int m00 = msks[mbase + lr] != 0,      m01 = msks[mbase + lr + 8] != 0;
        const int m10 = msks[mbase + 16 + lr] != 0, m11 = msks[mbase + 24 + lr] != 0;

        #pragma unroll
        for (int mi = 0; mi < 2; ++mi)
            #pragma unroll
            for (int nf = 0; nf < 4; ++nf)
                #pragma unroll
                for (int e = 0; e < 4; ++e) acc[mi][nf][e] = 0.0f;

        #pragma unroll 1
        for (int s = 0; s < 8; ++s) {
            uint32_t ah[2][4], al[2][4];
            const int w0 = 8 * s + lkb;
            #pragma unroll
            for (int mi = 0; mi < 2; ++mi) {
                const int r = mbase + 16 * mi + lrow;
                ldm4(ah[mi], sb + SM_HHI + 4 * hword(r, w0));
                ldm4(al[mi], sb + SM_HLO + 4 * hword(r, w0));
            }
            #pragma unroll
            for (int nf = 0; nf < 4; ++nf) {
                const uint4 B = __ldg(&g_bfrag[(s * 16 + nq * 4 + nf) * 32 + lane]);
                #pragma unroll
                for (int mi = 0; mi < 2; ++mi) {
                    mma16816(acc[mi][nf], ah[mi], B.x, B.y);
                    mma16816(acc[mi][nf], ah[mi], B.z, B.w);
                    mma16816(acc[mi][nf], al[mi], B.x, B.y);
                }
            }
        }

        // ---- epilogue-2: masked max over the warp's 32 points ----
        #pragma unroll
        for (int nf = 0; nf < 4; ++nf) {
            float e0 = NEG_INF_F, e1 = NEG_INF_F;
            if (m00) { e0 = fmaxf(e0, acc[0][nf][0]); e1 = fmaxf(e1, acc[0][nf][1]); }
            if (m01) { e0 = fmaxf(e0, acc[0][nf][2]); e1 = fmaxf(e1, acc[0][nf][3]); }
            if (m10) { e0 = fmaxf(e0, acc[1][nf][0]); e1 = fmaxf(e1, acc[1][nf][1]); }
            if (m11) { e0 = fmaxf(e0, acc[1][nf][2]); e1 = fmaxf(e1, acc[1][nf][3]); }
            #pragma unroll
            for (int off = 4; off < 32; off <<= 1) {
                e0 = fmaxf(e0, __shfl_xor_sync(0xffffffffu, e0, off));
                e1 = fmaxf(e1, __shfl_xor_sync(0xffffffffu, e1, off));
            }
            if (lane < 4) {
                const int n = nq * 32 + nf * 8 + 2 * lane;
                red[mq * 128 + n]     = e0;
                red[mq * 128 + n + 1] = e1;
            }
        }
        __syncthreads();       // bar #3

        // ---- final: combine 2 M-quads, +b2, any-valid (1 polyline/tile) ----
        if (tid < 128) {
            const float v = fmaxf(red[tid], red[128 + tid]);
            const uint32_t av = flgs[0] | flgs[1];
            out[(size_t)tile * 128 + tid] = av ? v + b2g[tid] : 0.0f;
        }

        buf ^= 1;
    }
}

extern "C" void kernel_launch(void* const* d_in, const int* in_sizes, int n_in,
                              void* d_out, int out_size)
{
    const float* poly = (const float*)d_in[0];
    const int*   mask = (const int*)  d_in[1];
    const float* W1   = (const float*)d_in[2];
    const float* b1   = (const float*)d_in[3];
    const float* W2   = (const float*)d_in[4];
    const float* b2   = (const float*)d_in[5];
    float* out = (float*)d_out;

    const int npoints = in_sizes[0] / 9;           // 1,048,576
    const int ntiles  = npoints / TILE_PTS;        // 16384

    prep_kernel<<<16, 256>>>(W1, W2);

    cudaFuncSetAttribute(poly_mma_kernel,
                         cudaFuncAttributeMaxDynamicSharedMemorySize, SM_BYTES);
    poly_mma_kernel<<<444, NT, SM_BYTES>>>(poly, mask, b1, b2, out, ntiles);
}